// round 8
// baseline (speedup 1.0000x reference)
#include <cuda_runtime.h>
#include <cuda_fp16.h>
#include <cstdint>

// ============================================================================
// GFDreConv: out[b,o,h,w] = sum_{k<2304} W[o,k] * X[k](b,h,w)
// Single-pass fp16 mma.sync m16n8k16, fp32 accum (rel_err ~3e-4 < 1e-3).
// feat transposed to [b][sp][c] fp16 so gathered K-runs are contiguous.
// This round: 2-stage pipeline (76KB smem) + 3 CTAs/SM (24 warps) to fix the
// latency-bound profile (tensor 35.8%, issue 12.1% at 2 CTAs/SM).
// ============================================================================

#define KTOT 2304
#define BK   64
#define NC   (KTOT / BK)   // 36

__device__ __align__(16) __half g_Wh[256 * KTOT];
__device__ __align__(16) __half g_Fh[8ull * 4096 * 256];     // 16 MB, L2-resident

// smem rows: 64 halves + 8 pad = 72 halves (144B): ldmatrix phase stride 9,
// coprime with 8 banks -> conflict-free.
#define LDS_ROW 72
#define STAGE_H (128 * LDS_ROW)            // halves per (A or B) stage: 9216
#define STAGE_B (STAGE_H * 2)              // 18432 B
#define OFF_A   0                          // 2 stages A: 36864 B
#define OFF_B   (2 * STAGE_B)              // 2 stages B: 36864 B
#define OFF_GO  (4 * STAGE_B)              // 9*128 u16 = 2304 B
#define SMEM_TOTAL (OFF_GO + 9 * 128 * 2)  // 76032 B -> 3 CTAs/SM (228KB)

#define FPREP_SMEM (256 * 64 * 4)          // 64 KB dynamic

__device__ __forceinline__ uint32_t s2u(const void* p) {
    uint32_t a;
    asm("{ .reg .u64 t; cvta.to.shared.u64 t, %1; cvt.u32.u64 %0, t; }" : "=r"(a) : "l"(p));
    return a;
}
__device__ __forceinline__ void cpa(uint32_t d, const void* g) {
    asm volatile("cp.async.cg.shared.global [%0], [%1], 16;" :: "r"(d), "l"(g));
}

#define LDSM4(r, a)                                                            \
    asm volatile("ldmatrix.sync.aligned.m8n8.x4.shared.b16 {%0,%1,%2,%3},[%4];"\
                 : "=r"((r)[0]), "=r"((r)[1]), "=r"((r)[2]), "=r"((r)[3])      \
                 : "r"(a))
#define MMA(c, a, b0, b1)                                                      \
    asm volatile("mma.sync.aligned.m16n8k16.row.col.f32.f16.f16.f32 "          \
                 "{%0,%1,%2,%3},{%4,%5,%6,%7},{%8,%9},{%0,%1,%2,%3};"          \
                 : "+f"((c)[0]), "+f"((c)[1]), "+f"((c)[2]), "+f"((c)[3])      \
                 : "r"((a)[0]), "r"((a)[1]), "r"((a)[2]), "r"((a)[3]),         \
                   "r"(b0), "r"(b1))

// ---------------------------------------------------------------------------
// Fused prep. Blocks [0,512): transpose feat (b,y slice) -> [b][sp][c] fp16.
// Blocks [512,800): W -> fp16 (2048 elems/block, vectorized).
// ---------------------------------------------------------------------------
__global__ void __launch_bounds__(256, 1)
prep(const float* __restrict__ feat, const float* __restrict__ Wc) {
    const int t = threadIdx.x;
    if (blockIdx.x >= 512) {
        const int base = (blockIdx.x - 512) * 2048 + t * 8;
        float4 v0 = *(const float4*)(Wc + base);
        float4 v1 = *(const float4*)(Wc + base + 4);
        __half hb[8];
        hb[0] = __float2half(v0.x); hb[1] = __float2half(v0.y);
        hb[2] = __float2half(v0.z); hb[3] = __float2half(v0.w);
        hb[4] = __float2half(v1.x); hb[5] = __float2half(v1.y);
        hb[6] = __float2half(v1.z); hb[7] = __float2half(v1.w);
        *(uint4*)(g_Wh + base) = *(const uint4*)hb;
        return;
    }
    extern __shared__ float tile[];      // [c][x] 256*64 f32
    const int b = blockIdx.x >> 6;
    const int y = blockIdx.x & 63;
    const float* src = feat + (((size_t)b * 256) * 64 + y) * 64;
    for (int idx = t; idx < 256 * 64; idx += 256) {
        int c = idx >> 6, x = idx & 63;
        tile[idx] = src[(size_t)c * 4096 + x];
    }
    __syncthreads();
    const int x = t >> 2;
    const int c0 = (t & 3) * 64;
    uint4* dh = (uint4*)(g_Fh + ((size_t)b * 4096 + (size_t)y * 64 + x) * 256 + c0);
#pragma unroll
    for (int j = 0; j < 8; j++) {
        __half hbuf[8];
#pragma unroll
        for (int i = 0; i < 8; i++)
            hbuf[i] = __float2half(tile[(c0 + j * 8 + i) * 64 + x]);
        dh[j] = *(const uint4*)hbuf;
    }
}

// ---------------------------------------------------------------------------
// Main: 512 CTAs (2 M x 256 N-blocks), 256 threads (8 warps 4Mx2N), 3 CTA/SM.
// 2-stage cp.async pipeline, single __syncthreads per chunk, depth-1 prefetch.
// ---------------------------------------------------------------------------
__global__ void __launch_bounds__(256, 3)
gfd_mma(const int* __restrict__ sx, const int* __restrict__ sy,
        float* __restrict__ out) {
    extern __shared__ char sm[];
    const uint32_t sb = s2u(sm);

    const int t = threadIdx.x, lane = t & 31, wid = t >> 5;
    const int wm = wid & 3, wn = wid >> 2;
    const int mblk = blockIdx.x & 1, nblk = blockIdx.x >> 1;
    const int b = nblk >> 5;
    const int sp0 = (nblk & 31) * 128;

    uint16_t* gofs = (uint16_t*)(sm + OFF_GO);
    for (int i = t; i < 9 * 128; i += 256) {
        int s = i >> 7, nn = i & 127;
        int sp = sp0 + nn;
        int v;
        if (s == 0) v = sp;
        else {
            int idx = sp * 8 + (s - 1);
            v = (sy[idx] - 1) * 64 + (sx[idx] - 1);
        }
        gofs[i] = (uint16_t)v;
    }
    __syncthreads();

    const int arow = t >> 1;              // 0..127
    const int hsel = (t & 1) * 32;        // half-row (in halves)
    const size_t fb = (size_t)b * 4096 * 256;
    const __half* wbase = g_Wh + (size_t)(mblk * 128) * KTOT;

    float acc[2][8][4];
#pragma unroll
    for (int i = 0; i < 2; i++)
#pragma unroll
        for (int j = 0; j < 8; j++)
#pragma unroll
            for (int q = 0; q < 4; q++) acc[i][j][q] = 0.0f;

    auto issue = [&](int kc) {
        const int stg = kc & 1;
        const int k0 = kc * BK;
        const int s = kc >> 2;
        const int c0 = (kc & 3) * 64;
        const uint32_t dbase =
            ((uint32_t)stg * STAGE_H + (uint32_t)arow * LDS_ROW + hsel) * 2;
        const __half* ga = wbase + (size_t)arow * KTOT + k0 + hsel;
#pragma unroll
        for (int q = 0; q < 4; q++)
            cpa(sb + OFF_A + dbase + q * 16, ga + q * 8);
        const int sp = gofs[s * 128 + arow];
        const __half* gb = g_Fh + fb + (size_t)sp * 256 + c0 + hsel;
#pragma unroll
        for (int q = 0; q < 4; q++)
            cpa(sb + OFF_B + dbase + q * 16, gb + q * 8);
        asm volatile("cp.async.commit_group;" ::: "memory");
    };

    issue(0);

    for (int kc = 0; kc < NC; kc++) {
        asm volatile("cp.async.wait_group 0;" ::: "memory");
        __syncthreads();
        if (kc + 1 < NC) issue(kc + 1);   // overwrites stage of kc-1 (done)

        const int stg = kc & 1;
        const uint32_t aP = sb + OFF_A + (uint32_t)stg * STAGE_B;
        const uint32_t bP = sb + OFF_B + (uint32_t)stg * STAGE_B;

#pragma unroll
        for (int kk = 0; kk < 4; kk++) {
            uint32_t ah[2][4];
#pragma unroll
            for (int i = 0; i < 2; i++) {
                const int row = wm * 32 + i * 16 + (lane & 15);
                const uint32_t off =
                    ((uint32_t)row * LDS_ROW + kk * 16 + (lane >> 4) * 8) * 2;
                LDSM4(ah[i], aP + off);
            }
#pragma unroll
            for (int j2 = 0; j2 < 4; j2++) {
                const int rowb = wn * 64 + j2 * 16 + (lane >> 4) * 8 + (lane & 7);
                const uint32_t off =
                    ((uint32_t)rowb * LDS_ROW + kk * 16 + ((lane >> 3) & 1) * 8) * 2;
                uint32_t bf[4];
                LDSM4(bf, bP + off);
                MMA(acc[0][j2 * 2],     ah[0], bf[0], bf[1]);
                MMA(acc[1][j2 * 2],     ah[1], bf[0], bf[1]);
                MMA(acc[0][j2 * 2 + 1], ah[0], bf[2], bf[3]);
                MMA(acc[1][j2 * 2 + 1], ah[1], bf[2], bf[3]);
            }
        }
    }

    const int g = lane >> 2, tig = lane & 3;
#pragma unroll
    for (int i = 0; i < 2; i++) {
        const int o = mblk * 128 + wm * 32 + i * 16 + g;
        float* obase = out + ((size_t)b * 256 + o) * 4096;
#pragma unroll
        for (int j = 0; j < 8; j++) {
            const int sp = sp0 + wn * 64 + j * 8 + tig * 2;
            *(float2*)(obase + sp) = make_float2(acc[i][j][0], acc[i][j][1]);
            *(float2*)(obase + 8 * 4096 + sp) = make_float2(acc[i][j][2], acc[i][j][3]);
        }
    }
}

// ============================================================================
extern "C" void kernel_launch(void* const* d_in, const int* in_sizes, int n_in,
                              void* d_out, int out_size) {
    const float* feat = (const float*)d_in[0];  // (8,256,64,64) f32
    const float* Wc   = (const float*)d_in[1];  // (256,2304) f32
    const int*   sx   = (const int*)d_in[2];    // (64,64,8) i32
    const int*   sy   = (const int*)d_in[3];    // (64,64,8) i32
    float*       out  = (float*)d_out;          // (8,256,64,64) f32

    static bool attr_set = false;
    if (!attr_set) {
        cudaFuncSetAttribute(gfd_mma, cudaFuncAttributeMaxDynamicSharedMemorySize,
                             SMEM_TOTAL);
        cudaFuncSetAttribute(prep, cudaFuncAttributeMaxDynamicSharedMemorySize,
                             FPREP_SMEM);
        attr_set = true;
    }

    prep<<<800, 256, FPREP_SMEM>>>(feat, Wc);
    gfd_mma<<<512, 256, SMEM_TOTAL>>>(sx, sy, out);
}

// round 9
// speedup vs baseline: 1.5842x; 1.5842x over previous
#include <cuda_runtime.h>
#include <cuda_fp16.h>
#include <cstdint>

// ============================================================================
// GFDreConv: out[b,o,h,w] = sum_{k<2304} W[o,k] * X[k](b,h,w)
// Single-pass fp16 mma.sync m16n8k16, fp32 accum (rel_err ~3e-4 < 1e-3).
// feat transposed to [b][sp][c] fp16 so gathered K-runs are contiguous.
// Round 9: round-7 config (3-stage, 2 CTA/SM, 126 regs) + explicit register
// double-buffering of A/B fragments across kk-steps to hide ldmatrix latency.
// ============================================================================

#define KTOT 2304
#define BK   64
#define NC   (KTOT / BK)   // 36

__device__ __align__(16) __half g_Wh[256 * KTOT];
__device__ __align__(16) __half g_Fh[8ull * 4096 * 256];     // 16 MB, L2-resident

// smem rows: 64 halves + 8 pad = 72 halves (144B): ldmatrix rows stride 36
// words -> banks 4r..4r+3 for r=0..7, conflict-free.
#define LDS_ROW 72
#define STAGE_H (128 * LDS_ROW)            // halves per (A or B) stage: 9216
#define STAGE_B (STAGE_H * 2)              // 18432 B
#define OFF_A   0                          // 3 stages A: 55296 B
#define OFF_B   (3 * STAGE_B)              // 3 stages B: 55296 B
#define OFF_GO  (6 * STAGE_B)              // 9*128 u16 = 2304 B
#define SMEM_TOTAL (OFF_GO + 9 * 128 * 2)  // 112896 B -> 2 CTAs/SM

#define FPREP_SMEM (256 * 64 * 4)          // 64 KB dynamic

__device__ __forceinline__ uint32_t s2u(const void* p) {
    uint32_t a;
    asm("{ .reg .u64 t; cvta.to.shared.u64 t, %1; cvt.u32.u64 %0, t; }" : "=r"(a) : "l"(p));
    return a;
}
__device__ __forceinline__ void cpa(uint32_t d, const void* g) {
    asm volatile("cp.async.cg.shared.global [%0], [%1], 16;" :: "r"(d), "l"(g));
}

#define LDSM4(r, a)                                                            \
    asm volatile("ldmatrix.sync.aligned.m8n8.x4.shared.b16 {%0,%1,%2,%3},[%4];"\
                 : "=r"((r)[0]), "=r"((r)[1]), "=r"((r)[2]), "=r"((r)[3])      \
                 : "r"(a))
#define MMA(c, a, b0, b1)                                                      \
    asm volatile("mma.sync.aligned.m16n8k16.row.col.f32.f16.f16.f32 "          \
                 "{%0,%1,%2,%3},{%4,%5,%6,%7},{%8,%9},{%0,%1,%2,%3};"          \
                 : "+f"((c)[0]), "+f"((c)[1]), "+f"((c)[2]), "+f"((c)[3])      \
                 : "r"((a)[0]), "r"((a)[1]), "r"((a)[2]), "r"((a)[3]),         \
                   "r"(b0), "r"(b1))

// ---------------------------------------------------------------------------
// Fused prep. Blocks [0,512): transpose feat (b,y slice) -> [b][sp][c] fp16.
// Blocks [512,800): W -> fp16.
// ---------------------------------------------------------------------------
__global__ void __launch_bounds__(256, 1)
prep(const float* __restrict__ feat, const float* __restrict__ Wc) {
    const int t = threadIdx.x;
    if (blockIdx.x >= 512) {
        const int base = (blockIdx.x - 512) * 2048 + t * 8;
        float4 v0 = *(const float4*)(Wc + base);
        float4 v1 = *(const float4*)(Wc + base + 4);
        __half hb[8];
        hb[0] = __float2half(v0.x); hb[1] = __float2half(v0.y);
        hb[2] = __float2half(v0.z); hb[3] = __float2half(v0.w);
        hb[4] = __float2half(v1.x); hb[5] = __float2half(v1.y);
        hb[6] = __float2half(v1.z); hb[7] = __float2half(v1.w);
        *(uint4*)(g_Wh + base) = *(const uint4*)hb;
        return;
    }
    extern __shared__ float tile[];      // [c][x] 256*64 f32
    const int b = blockIdx.x >> 6;
    const int y = blockIdx.x & 63;
    const float* src = feat + (((size_t)b * 256) * 64 + y) * 64;
    for (int idx = t; idx < 256 * 64; idx += 256) {
        int c = idx >> 6, x = idx & 63;
        tile[idx] = src[(size_t)c * 4096 + x];
    }
    __syncthreads();
    const int x = t >> 2;
    const int c0 = (t & 3) * 64;
    uint4* dh = (uint4*)(g_Fh + ((size_t)b * 4096 + (size_t)y * 64 + x) * 256 + c0);
#pragma unroll
    for (int j = 0; j < 8; j++) {
        __half hbuf[8];
#pragma unroll
        for (int i = 0; i < 8; i++)
            hbuf[i] = __float2half(tile[(c0 + j * 8 + i) * 64 + x]);
        dh[j] = *(const uint4*)hbuf;
    }
}

// ---------------------------------------------------------------------------
// Main: 512 CTAs (2 M x 256 N-blocks), 256 threads (8 warps 4Mx2N), 2 CTA/SM.
// 3-stage cp.async pipeline + register double-buffered fragments.
// ---------------------------------------------------------------------------
__global__ void __launch_bounds__(256, 2)
gfd_mma(const int* __restrict__ sx, const int* __restrict__ sy,
        float* __restrict__ out) {
    extern __shared__ char sm[];
    const uint32_t sb = s2u(sm);

    const int t = threadIdx.x, lane = t & 31, wid = t >> 5;
    const int wm = wid & 3, wn = wid >> 2;
    const int mblk = blockIdx.x & 1, nblk = blockIdx.x >> 1;
    const int b = nblk >> 5;
    const int sp0 = (nblk & 31) * 128;

    uint16_t* gofs = (uint16_t*)(sm + OFF_GO);
    for (int i = t; i < 9 * 128; i += 256) {
        int s = i >> 7, nn = i & 127;
        int sp = sp0 + nn;
        int v;
        if (s == 0) v = sp;
        else {
            int idx = sp * 8 + (s - 1);
            v = (sy[idx] - 1) * 64 + (sx[idx] - 1);
        }
        gofs[i] = (uint16_t)v;
    }
    __syncthreads();

    const int arow = t >> 1;              // 0..127
    const int hsel = (t & 1) * 32;        // half-row (in halves)
    const size_t fb = (size_t)b * 4096 * 256;
    const __half* wbase = g_Wh + (size_t)(mblk * 128) * KTOT;

    // precomputed ldmatrix base offsets (halves*2 = bytes)
    const uint32_t a_off0 =
        ((uint32_t)(wm * 32 + (lane & 15)) * LDS_ROW + (lane >> 4) * 8) * 2;
    const uint32_t a_off1 = a_off0 + (uint32_t)(16 * LDS_ROW) * 2;
    const uint32_t b_base =
        ((uint32_t)(wn * 64 + (lane >> 4) * 8 + (lane & 7)) * LDS_ROW +
         ((lane >> 3) & 1) * 8) * 2;

    float acc[2][8][4];
#pragma unroll
    for (int i = 0; i < 2; i++)
#pragma unroll
        for (int j = 0; j < 8; j++)
#pragma unroll
            for (int q = 0; q < 4; q++) acc[i][j][q] = 0.0f;

    auto issue = [&](int kc) {
        const int stg = kc % 3;
        const int k0 = kc * BK;
        const int s = kc >> 2;
        const int c0 = (kc & 3) * 64;
        const uint32_t dbase =
            ((uint32_t)stg * STAGE_H + (uint32_t)arow * LDS_ROW + hsel) * 2;
        const __half* ga = wbase + (size_t)arow * KTOT + k0 + hsel;
#pragma unroll
        for (int q = 0; q < 4; q++)
            cpa(sb + OFF_A + dbase + q * 16, ga + q * 8);
        const int sp = gofs[s * 128 + arow];
        const __half* gb = g_Fh + fb + (size_t)sp * 256 + c0 + hsel;
#pragma unroll
        for (int q = 0; q < 4; q++)
            cpa(sb + OFF_B + dbase + q * 16, gb + q * 8);
        asm volatile("cp.async.commit_group;" ::: "memory");
    };

    issue(0);
    issue(1);

    uint32_t ah[2][2][4];   // [set][i][4]
    uint32_t bf[2][4][4];   // [set][j2][4]

    for (int kc = 0; kc < NC; kc++) {
        if (kc == NC - 1) {
            asm volatile("cp.async.wait_group 0;" ::: "memory");
        } else {
            asm volatile("cp.async.wait_group 1;" ::: "memory");
        }
        __syncthreads();
        if (kc + 2 < NC) issue(kc + 2);

        const int stg = kc % 3;
        const uint32_t aP = sb + OFF_A + (uint32_t)stg * STAGE_B;
        const uint32_t bP = sb + OFF_B + (uint32_t)stg * STAGE_B;

        // ---- preload kk=0 fragments into set 0 ----
        LDSM4(ah[0][0], aP + a_off0);
        LDSM4(ah[0][1], aP + a_off1);
#pragma unroll
        for (int j2 = 0; j2 < 4; j2++)
            LDSM4(bf[0][j2], bP + b_base + (uint32_t)(j2 * 16 * LDS_ROW) * 2);

#pragma unroll
        for (int kk = 0; kk < 4; kk++) {
            const int cur = kk & 1, nxt = cur ^ 1;
            // ---- prefetch kk+1 fragments into the alternate set ----
            if (kk < 3) {
                const uint32_t ko = (uint32_t)((kk + 1) * 16) * 2;
                LDSM4(ah[nxt][0], aP + a_off0 + ko);
                LDSM4(ah[nxt][1], aP + a_off1 + ko);
#pragma unroll
                for (int j2 = 0; j2 < 4; j2++)
                    LDSM4(bf[nxt][j2],
                          bP + b_base + (uint32_t)(j2 * 16 * LDS_ROW) * 2 + ko);
            }
            // ---- 16 MMAs on the current set ----
#pragma unroll
            for (int j2 = 0; j2 < 4; j2++) {
                MMA(acc[0][j2 * 2],     ah[cur][0], bf[cur][j2][0], bf[cur][j2][1]);
                MMA(acc[1][j2 * 2],     ah[cur][1], bf[cur][j2][0], bf[cur][j2][1]);
                MMA(acc[0][j2 * 2 + 1], ah[cur][0], bf[cur][j2][2], bf[cur][j2][3]);
                MMA(acc[1][j2 * 2 + 1], ah[cur][1], bf[cur][j2][2], bf[cur][j2][3]);
            }
        }
    }

    const int g = lane >> 2, tig = lane & 3;
#pragma unroll
    for (int i = 0; i < 2; i++) {
        const int o = mblk * 128 + wm * 32 + i * 16 + g;
        float* obase = out + ((size_t)b * 256 + o) * 4096;
#pragma unroll
        for (int j = 0; j < 8; j++) {
            const int sp = sp0 + wn * 64 + j * 8 + tig * 2;
            *(float2*)(obase + sp) = make_float2(acc[i][j][0], acc[i][j][1]);
            *(float2*)(obase + 8 * 4096 + sp) = make_float2(acc[i][j][2], acc[i][j][3]);
        }
    }
}

// ============================================================================
extern "C" void kernel_launch(void* const* d_in, const int* in_sizes, int n_in,
                              void* d_out, int out_size) {
    const float* feat = (const float*)d_in[0];  // (8,256,64,64) f32
    const float* Wc   = (const float*)d_in[1];  // (256,2304) f32
    const int*   sx   = (const int*)d_in[2];    // (64,64,8) i32
    const int*   sy   = (const int*)d_in[3];    // (64,64,8) i32
    float*       out  = (float*)d_out;          // (8,256,64,64) f32

    static bool attr_set = false;
    if (!attr_set) {
        cudaFuncSetAttribute(gfd_mma, cudaFuncAttributeMaxDynamicSharedMemorySize,
                             SMEM_TOTAL);
        cudaFuncSetAttribute(prep, cudaFuncAttributeMaxDynamicSharedMemorySize,
                             FPREP_SMEM);
        attr_set = true;
    }

    prep<<<800, 256, FPREP_SMEM>>>(feat, Wc);
    gfd_mma<<<512, 256, SMEM_TOTAL>>>(sx, sy, out);
}

// round 10
// speedup vs baseline: 1.6455x; 1.0387x over previous
#include <cuda_runtime.h>
#include <cuda_fp16.h>
#include <cstdint>

// ============================================================================
// GFDreConv: out[b,o,h,w] = sum_{k<2304} W[o,k] * X[k](b,h,w)
// Single-pass fp16 mma.sync m16n8k16, fp32 accum (rel_err ~3e-4 < 1e-3).
// feat transposed to [b][sp][c] fp16 so gathered K-runs are contiguous.
// Round 10: CTA tile 128x64, warp tile 32x32 (acc=32 regs) -> 3 CTAs/SM,
// 24 warps, no spills (85-reg cap vs ~70 need). Fixes warp starvation.
// ============================================================================

#define KTOT 2304
#define BK   64
#define NC   (KTOT / BK)   // 36

__device__ __align__(16) __half g_Wh[256 * KTOT];
__device__ __align__(16) __half g_Fh[8ull * 4096 * 256];     // 16 MB, L2-resident

// smem rows: 64 halves + 8 pad = 72 halves (144B), conflict-free for ldmatrix.
#define LDS_ROW 72
// A stage: 128 rows, B stage: 64 rows (bytes):
#define A_STG_B (128 * LDS_ROW * 2)        // 18432
#define B_STG_B (64 * LDS_ROW * 2)         // 9216
#define OFF_B0  (2 * A_STG_B)              // B stages after 2 A stages
#define OFF_GO  (2 * A_STG_B + 2 * B_STG_B)        // 55296
#define SMEM_TOTAL (OFF_GO + 9 * 64 * 2)   // 56448 B -> 3 CTAs/SM (169KB)

#define FPREP_SMEM (256 * 64 * 4)          // 64 KB dynamic

__device__ __forceinline__ uint32_t s2u(const void* p) {
    uint32_t a;
    asm("{ .reg .u64 t; cvta.to.shared.u64 t, %1; cvt.u32.u64 %0, t; }" : "=r"(a) : "l"(p));
    return a;
}
__device__ __forceinline__ void cpa(uint32_t d, const void* g) {
    asm volatile("cp.async.cg.shared.global [%0], [%1], 16;" :: "r"(d), "l"(g));
}

#define LDSM4(r, a)                                                            \
    asm volatile("ldmatrix.sync.aligned.m8n8.x4.shared.b16 {%0,%1,%2,%3},[%4];"\
                 : "=r"((r)[0]), "=r"((r)[1]), "=r"((r)[2]), "=r"((r)[3])      \
                 : "r"(a))
#define MMA(c, a, b0, b1)                                                      \
    asm volatile("mma.sync.aligned.m16n8k16.row.col.f32.f16.f16.f32 "          \
                 "{%0,%1,%2,%3},{%4,%5,%6,%7},{%8,%9},{%0,%1,%2,%3};"          \
                 : "+f"((c)[0]), "+f"((c)[1]), "+f"((c)[2]), "+f"((c)[3])      \
                 : "r"((a)[0]), "r"((a)[1]), "r"((a)[2]), "r"((a)[3]),         \
                   "r"(b0), "r"(b1))

// ---------------------------------------------------------------------------
// Fused prep. Blocks [0,512): transpose feat (b,y slice) -> [b][sp][c] fp16.
// Blocks [512,800): W -> fp16.
// ---------------------------------------------------------------------------
__global__ void __launch_bounds__(256, 1)
prep(const float* __restrict__ feat, const float* __restrict__ Wc) {
    const int t = threadIdx.x;
    if (blockIdx.x >= 512) {
        const int base = (blockIdx.x - 512) * 2048 + t * 8;
        float4 v0 = *(const float4*)(Wc + base);
        float4 v1 = *(const float4*)(Wc + base + 4);
        __half hb[8];
        hb[0] = __float2half(v0.x); hb[1] = __float2half(v0.y);
        hb[2] = __float2half(v0.z); hb[3] = __float2half(v0.w);
        hb[4] = __float2half(v1.x); hb[5] = __float2half(v1.y);
        hb[6] = __float2half(v1.z); hb[7] = __float2half(v1.w);
        *(uint4*)(g_Wh + base) = *(const uint4*)hb;
        return;
    }
    extern __shared__ float tile[];      // [c][x] 256*64 f32
    const int b = blockIdx.x >> 6;
    const int y = blockIdx.x & 63;
    const float* src = feat + (((size_t)b * 256) * 64 + y) * 64;
    for (int idx = t; idx < 256 * 64; idx += 256) {
        int c = idx >> 6, x = idx & 63;
        tile[idx] = src[(size_t)c * 4096 + x];
    }
    __syncthreads();
    const int x = t >> 2;
    const int c0 = (t & 3) * 64;
    uint4* dh = (uint4*)(g_Fh + ((size_t)b * 4096 + (size_t)y * 64 + x) * 256 + c0);
#pragma unroll
    for (int j = 0; j < 8; j++) {
        __half hbuf[8];
#pragma unroll
        for (int i = 0; i < 8; i++)
            hbuf[i] = __float2half(tile[(c0 + j * 8 + i) * 64 + x]);
        dh[j] = *(const uint4*)hbuf;
    }
}

// ---------------------------------------------------------------------------
// Main: 1024 CTAs (2 M-blocks x 512 N-blocks of 64), 256 threads,
// 8 warps (4M x 2N), warp tile 32x32, 3 CTAs/SM, 2-stage pipeline.
// ---------------------------------------------------------------------------
__global__ void __launch_bounds__(256, 3)
gfd_mma(const int* __restrict__ sx, const int* __restrict__ sy,
        float* __restrict__ out) {
    extern __shared__ char sm[];
    const uint32_t sb = s2u(sm);

    const int t = threadIdx.x, lane = t & 31, wid = t >> 5;
    const int wm = wid & 3, wn = wid >> 2;           // 4M x 2N
    const int mblk = blockIdx.x & 1;
    const int r = blockIdx.x >> 1;
    const int b = r >> 6;
    const int n0 = (r & 63) * 64;

    uint16_t* gofs = (uint16_t*)(sm + OFF_GO);
    for (int i = t; i < 9 * 64; i += 256) {
        int s = i >> 6, nn = i & 63;
        int sp = n0 + nn;
        int v;
        if (s == 0) v = sp;
        else {
            int idx = sp * 8 + (s - 1);
            v = (sy[idx] - 1) * 64 + (sx[idx] - 1);
        }
        gofs[i] = (uint16_t)v;
    }
    __syncthreads();

    // A load map: row = t>>1 (0..127), 64B half-row; B: row = t>>2 (0..63), 32B
    const int a_row = t >> 1, a_h = (t & 1) * 32;
    const int b_row = t >> 2, b_q = (t & 3) * 16;
    const size_t fb = (size_t)b * 4096 * 256;
    const __half* wbase = g_Wh + (size_t)(mblk * 128) * KTOT;

    // ldmatrix offsets
    const uint32_t a_off0 =
        ((uint32_t)(wm * 32 + (lane & 15)) * LDS_ROW + (lane >> 4) * 8) * 2;
    const uint32_t a_off1 = a_off0 + (uint32_t)(16 * LDS_ROW) * 2;
    const uint32_t b_off0 =
        ((uint32_t)(wn * 32 + (lane >> 4) * 8 + (lane & 7)) * LDS_ROW +
         ((lane >> 3) & 1) * 8) * 2;
    const uint32_t b_off1 = b_off0 + (uint32_t)(16 * LDS_ROW) * 2;

    float acc[2][4][4];
#pragma unroll
    for (int i = 0; i < 2; i++)
#pragma unroll
        for (int j = 0; j < 4; j++)
#pragma unroll
            for (int q = 0; q < 4; q++) acc[i][j][q] = 0.0f;

    auto issue = [&](int kc) {
        const int stg = kc & 1;
        const int k0 = kc * BK;
        const int s = kc >> 2;
        const int c0 = (kc & 3) * 64;
        // A
        const uint32_t da = sb + stg * A_STG_B + ((uint32_t)a_row * LDS_ROW + a_h) * 2;
        const __half* ga = wbase + (size_t)a_row * KTOT + k0 + a_h;
#pragma unroll
        for (int q = 0; q < 4; q++) cpa(da + q * 16, ga + q * 8);
        // B (gathered)
        const int sp = gofs[s * 64 + b_row];
        const uint32_t db = sb + OFF_B0 + stg * B_STG_B +
                            ((uint32_t)b_row * LDS_ROW + b_q) * 2;
        const __half* gb = g_Fh + fb + (size_t)sp * 256 + c0 + b_q;
#pragma unroll
        for (int q = 0; q < 2; q++) cpa(db + q * 16, gb + q * 8);
        asm volatile("cp.async.commit_group;" ::: "memory");
    };

    issue(0);

    for (int kc = 0; kc < NC; kc++) {
        asm volatile("cp.async.wait_group 0;" ::: "memory");
        __syncthreads();
        if (kc + 1 < NC) issue(kc + 1);

        const int stg = kc & 1;
        const uint32_t aP = sb + stg * A_STG_B;
        const uint32_t bP = sb + OFF_B0 + stg * B_STG_B;

#pragma unroll
        for (int kk = 0; kk < 4; kk++) {
            const uint32_t ko = (uint32_t)(kk * 16) * 2;
            uint32_t ah[2][4], bf[2][4];
            LDSM4(ah[0], aP + a_off0 + ko);
            LDSM4(ah[1], aP + a_off1 + ko);
            LDSM4(bf[0], bP + b_off0 + ko);
            LDSM4(bf[1], bP + b_off1 + ko);
#pragma unroll
            for (int j2 = 0; j2 < 2; j2++) {
#pragma unroll
                for (int i = 0; i < 2; i++) {
                    MMA(acc[i][j2 * 2],     ah[i], bf[j2][0], bf[j2][1]);
                    MMA(acc[i][j2 * 2 + 1], ah[i], bf[j2][2], bf[j2][3]);
                }
            }
        }
    }

    const int g = lane >> 2, tig = lane & 3;
#pragma unroll
    for (int i = 0; i < 2; i++) {
        const int o = mblk * 128 + wm * 32 + i * 16 + g;
        float* obase = out + ((size_t)b * 256 + o) * 4096;
#pragma unroll
        for (int j = 0; j < 4; j++) {
            const int sp = n0 + wn * 32 + j * 8 + tig * 2;
            *(float2*)(obase + sp) = make_float2(acc[i][j][0], acc[i][j][1]);
            *(float2*)(obase + 8 * 4096 + sp) = make_float2(acc[i][j][2], acc[i][j][3]);
        }
    }
}

// ============================================================================
extern "C" void kernel_launch(void* const* d_in, const int* in_sizes, int n_in,
                              void* d_out, int out_size) {
    const float* feat = (const float*)d_in[0];  // (8,256,64,64) f32
    const float* Wc   = (const float*)d_in[1];  // (256,2304) f32
    const int*   sx   = (const int*)d_in[2];    // (64,64,8) i32
    const int*   sy   = (const int*)d_in[3];    // (64,64,8) i32
    float*       out  = (float*)d_out;          // (8,256,64,64) f32

    static bool attr_set = false;
    if (!attr_set) {
        cudaFuncSetAttribute(gfd_mma, cudaFuncAttributeMaxDynamicSharedMemorySize,
                             SMEM_TOTAL);
        cudaFuncSetAttribute(prep, cudaFuncAttributeMaxDynamicSharedMemorySize,
                             FPREP_SMEM);
        attr_set = true;
    }

    prep<<<800, 256, FPREP_SMEM>>>(feat, Wc);
    gfd_mma<<<1024, 256, SMEM_TOTAL>>>(sx, sy, out);
}